// round 4
// baseline (speedup 1.0000x reference)
#include <cuda_runtime.h>

// ----------------------------------------------------------------------------
// MultiHeadAttention: out = softmax(mask((X Wq)(X Wk)^T * s)) (X Wv) Wo
// B=2, S=2048, D=768, H=12, hd=64, fp32 throughout.
// Stage 1: fused QKV projection GEMMs -> head-major scratch [B,H,S,64]
// Stage 2: flash-attention (Br=Bc=64, online softmax), exact reference masking:
//          causal ADDS -1e4 (future keys still participate in softmax!),
//          padding SETS -1e4. Blocks whose rows all-visible-padded extend the
//          KV loop over future tiles to match the reference exactly.
// Stage 3: output projection -> d_out
// ----------------------------------------------------------------------------

constexpr int BATCH = 2;
constexpr int SEQ   = 2048;
constexpr int DM    = 768;
constexpr int NH    = 12;
constexpr int HD    = 64;
constexpr int BH    = BATCH * NH;   // 24
constexpr int MTOT  = BATCH * SEQ;  // 4096
constexpr int NTILES = SEQ / 64;    // 32
constexpr float NEGV  = -10000.0f;
constexpr float SCALE = 0.125f;     // 1/sqrt(64)

// Scratch (allocation-free rule: __device__ globals)
__device__ float g_Q[BATCH * NH * SEQ * HD];
__device__ float g_K[BATCH * NH * SEQ * HD];
__device__ float g_V[BATCH * NH * SEQ * HD];
__device__ float g_O[BATCH * NH * SEQ * HD];

// ----------------------------------------------------------------------------
// Stage 1: QKV projections.  grid = (N/64, M/64, 3), 256 threads.
// ----------------------------------------------------------------------------
__global__ void __launch_bounds__(256) qkv_proj_kernel(
    const float* __restrict__ q, const float* __restrict__ k, const float* __restrict__ v,
    const float* __restrict__ Wq, const float* __restrict__ Wk, const float* __restrict__ Wv)
{
    __shared__ float As[64][17];
    __shared__ float Bs[16][64];

    const int z = blockIdx.z;
    const float* X = (z == 0) ? q : (z == 1) ? k : v;
    const float* W = (z == 0) ? Wq : (z == 1) ? Wk : Wv;
    float* out = (z == 0) ? g_Q : (z == 1) ? g_K : g_V;

    const int n0 = blockIdx.x * 64;   // head = blockIdx.x (TN==HD==64)
    const int m0 = blockIdx.y * 64;
    const int tid = threadIdx.x;
    const int tx = tid & 15, ty = tid >> 4;

    const int arow = tid >> 2, acol = (tid & 3) * 4;   // A tile load map
    const int brow = tid >> 4, bcol = (tid & 15) * 4;  // B tile load map

    float acc[4][4] = {};

    for (int k0 = 0; k0 < DM; k0 += 16) {
        float4 av = *reinterpret_cast<const float4*>(&X[(size_t)(m0 + arow) * DM + k0 + acol]);
        As[arow][acol + 0] = av.x;
        As[arow][acol + 1] = av.y;
        As[arow][acol + 2] = av.z;
        As[arow][acol + 3] = av.w;
        float4 bv = *reinterpret_cast<const float4*>(&W[(size_t)(k0 + brow) * DM + n0 + bcol]);
        *reinterpret_cast<float4*>(&Bs[brow][bcol]) = bv;
        __syncthreads();
        #pragma unroll
        for (int kk = 0; kk < 16; ++kk) {
            float a0 = As[ty * 4 + 0][kk];
            float a1 = As[ty * 4 + 1][kk];
            float a2 = As[ty * 4 + 2][kk];
            float a3 = As[ty * 4 + 3][kk];
            float4 b = *reinterpret_cast<float4*>(&Bs[kk][tx * 4]);
            acc[0][0] += a0 * b.x; acc[0][1] += a0 * b.y; acc[0][2] += a0 * b.z; acc[0][3] += a0 * b.w;
            acc[1][0] += a1 * b.x; acc[1][1] += a1 * b.y; acc[1][2] += a1 * b.z; acc[1][3] += a1 * b.w;
            acc[2][0] += a2 * b.x; acc[2][1] += a2 * b.y; acc[2][2] += a2 * b.z; acc[2][3] += a2 * b.w;
            acc[3][0] += a3 * b.x; acc[3][1] += a3 * b.y; acc[3][2] += a3 * b.z; acc[3][3] += a3 * b.w;
        }
        __syncthreads();
    }

    const int head = blockIdx.x;
    #pragma unroll
    for (int i = 0; i < 4; ++i) {
        int m = m0 + ty * 4 + i;
        int b = m >> 11;           // /SEQ
        int s = m & (SEQ - 1);
        float4 r = make_float4(acc[i][0], acc[i][1], acc[i][2], acc[i][3]);
        *reinterpret_cast<float4*>(&out[(((size_t)(b * NH + head)) * SEQ + s) * HD + tx * 4]) = r;
    }
}

// ----------------------------------------------------------------------------
// Stage 2: flash attention.  grid = (SEQ/64, B*H), 256 threads.
// Smem = 48KB: Qs[4096] + Kt[4096] + Vs[4096], Ps aliases Kt.
// ----------------------------------------------------------------------------
__global__ void __launch_bounds__(256) flash_kernel(
    const int* __restrict__ attn_mask, const int* __restrict__ mask_future)
{
    extern __shared__ float sm[];
    float* Qs = sm;                 // [64][64]
    float* Kt = sm + 4096;          // [64][64] (d-major: Kt[d*64 + j]); reused as Ps
    float* Vs = sm + 8192;          // [64][64]
    float* Ps = Kt;                 // alias: K dead after GEMM1

    const int tid = threadIdx.x;
    const int tx = tid & 15, ty = tid >> 4;
    const int rr = ty * 4, cc = tx * 4;
    const int qt = blockIdx.x;
    const int bh = blockIdx.y;
    const int b  = bh / NH;
    const int q0 = qt * 64;
    const bool causal = (mask_future[0] != 0);

    // load Q tile (row-major, float4)
    #pragma unroll
    for (int qd = 0; qd < 4; ++qd) {
        int fi = tid + qd * 256;
        int row = fi >> 4;
        int col = (fi & 15) * 4;
        *reinterpret_cast<float4*>(&Qs[row * 64 + col]) =
            *reinterpret_cast<const float4*>(&g_Q[(((size_t)bh) * SEQ + q0 + row) * HD + col]);
    }

    float m_i[4], l_i[4], o[4][4];
    #pragma unroll
    for (int i = 0; i < 4; ++i) {
        m_i[i] = -1e30f;
        l_i[i] = 0.0f;
        o[i][0] = o[i][1] = o[i][2] = o[i][3] = 0.0f;
    }

    // Causal: normally stop after the diagonal tile. But the reference softmax
    // spans ALL keys (future keys get raw*scale-1e4, padded keys exactly -1e4),
    // so if some row in this block has NO valid visible key, future keys carry
    // real softmax weight -> extend the loop. For normal rows the extension is
    // exact-zero (expf underflow), so extending for the whole block is safe.
    int limit = causal ? (qt + 1) : NTILES;

    for (int kt = 0; kt < NTILES; ++kt) {
        if (kt >= limit) break;
        const int k0 = kt * 64;
        __syncthreads();  // prior GEMM2 reads (Ps/Vs) done before overwriting Kt/Vs

        // K tile -> transposed smem (conflict-free scatter: j distinct per lane)
        {
            int j = tid & 63;
            int dq = (tid >> 6) * 16;
            #pragma unroll
            for (int qd = 0; qd < 4; ++qd) {
                int d = dq + qd * 4;
                float4 kv = *reinterpret_cast<const float4*>(
                    &g_K[(((size_t)bh) * SEQ + k0 + j) * HD + d]);
                Kt[(d + 0) * 64 + j] = kv.x;
                Kt[(d + 1) * 64 + j] = kv.y;
                Kt[(d + 2) * 64 + j] = kv.z;
                Kt[(d + 3) * 64 + j] = kv.w;
            }
        }
        // V tile (row-major)
        #pragma unroll
        for (int qd = 0; qd < 4; ++qd) {
            int fi = tid + qd * 256;
            int row = fi >> 4;
            int col = (fi & 15) * 4;
            *reinterpret_cast<float4*>(&Vs[row * 64 + col]) =
                *reinterpret_cast<const float4*>(&g_V[(((size_t)bh) * SEQ + k0 + row) * HD + col]);
        }
        // padding mask for this thread's 4 key columns (L1-cached broadcast)
        int mk[4];
        #pragma unroll
        for (int j = 0; j < 4; ++j)
            mk[j] = attn_mask[b * SEQ + k0 + cc + j];
        __syncthreads();

        // GEMM1: S = Q K^T  (4x4 per thread)
        float sacc[4][4] = {};
        #pragma unroll 16
        for (int d = 0; d < 64; ++d) {
            float a0 = Qs[(rr + 0) * 64 + d];
            float a1 = Qs[(rr + 1) * 64 + d];
            float a2 = Qs[(rr + 2) * 64 + d];
            float a3 = Qs[(rr + 3) * 64 + d];
            float4 kb = *reinterpret_cast<float4*>(&Kt[d * 64 + cc]);
            sacc[0][0] += a0 * kb.x; sacc[0][1] += a0 * kb.y; sacc[0][2] += a0 * kb.z; sacc[0][3] += a0 * kb.w;
            sacc[1][0] += a1 * kb.x; sacc[1][1] += a1 * kb.y; sacc[1][2] += a1 * kb.z; sacc[1][3] += a1 * kb.w;
            sacc[2][0] += a2 * kb.x; sacc[2][1] += a2 * kb.y; sacc[2][2] += a2 * kb.z; sacc[2][3] += a2 * kb.w;
            sacc[3][0] += a3 * kb.x; sacc[3][1] += a3 * kb.y; sacc[3][2] += a3 * kb.z; sacc[3][3] += a3 * kb.w;
        }
        __syncthreads();  // all Kt reads done before Ps (=Kt) writes below

        // scale + masks (reference order: scale, ADD causal NEG, then SET pad NEG)
        #pragma unroll
        for (int i = 0; i < 4; ++i) {
            int ig = q0 + rr + i;
            #pragma unroll
            for (int j = 0; j < 4; ++j) {
                int jg = k0 + cc + j;
                float sv = sacc[i][j] * SCALE;
                if (causal && jg > ig) sv += NEGV;
                if (mk[j] == 0) sv = NEGV;
                sacc[i][j] = sv;
            }
        }

        // online softmax per row (row spans 16 lanes: same ty group)
        #pragma unroll
        for (int i = 0; i < 4; ++i) {
            float tm = fmaxf(fmaxf(sacc[i][0], sacc[i][1]), fmaxf(sacc[i][2], sacc[i][3]));
            #pragma unroll
            for (int off = 8; off; off >>= 1)
                tm = fmaxf(tm, __shfl_xor_sync(0xffffffffu, tm, off));
            float mnew = fmaxf(m_i[i], tm);
            float alpha = __expf(m_i[i] - mnew);
            float ps = 0.0f;
            #pragma unroll
            for (int j = 0; j < 4; ++j) {
                float p = __expf(sacc[i][j] - mnew);
                sacc[i][j] = p;
                ps += p;
            }
            #pragma unroll
            for (int off = 8; off; off >>= 1)
                ps += __shfl_xor_sync(0xffffffffu, ps, off);
            l_i[i] = l_i[i] * alpha + ps;
            m_i[i] = mnew;
            o[i][0] *= alpha; o[i][1] *= alpha; o[i][2] *= alpha; o[i][3] *= alpha;
        }

        // write P to smem (aliased onto Kt)
        #pragma unroll
        for (int i = 0; i < 4; ++i)
            *reinterpret_cast<float4*>(&Ps[(rr + i) * 64 + cc]) =
                make_float4(sacc[i][0], sacc[i][1], sacc[i][2], sacc[i][3]);
        __syncthreads();

        // GEMM2: O += P V
        #pragma unroll 16
        for (int j = 0; j < 64; ++j) {
            float a0 = Ps[(rr + 0) * 64 + j];
            float a1 = Ps[(rr + 1) * 64 + j];
            float a2 = Ps[(rr + 2) * 64 + j];
            float a3 = Ps[(rr + 3) * 64 + j];
            float4 vv = *reinterpret_cast<float4*>(&Vs[j * 64 + cc]);
            o[0][0] += a0 * vv.x; o[0][1] += a0 * vv.y; o[0][2] += a0 * vv.z; o[0][3] += a0 * vv.w;
            o[1][0] += a1 * vv.x; o[1][1] += a1 * vv.y; o[1][2] += a1 * vv.z; o[1][3] += a1 * vv.w;
            o[2][0] += a2 * vv.x; o[2][1] += a2 * vv.y; o[2][2] += a2 * vv.z; o[2][3] += a2 * vv.w;
            o[3][0] += a3 * vv.x; o[3][1] += a3 * vv.y; o[3][2] += a3 * vv.z; o[3][3] += a3 * vv.w;
        }

        // After the diagonal tile: check if any row still has no valid visible
        // key (m_i == -1e4 exactly means every visible key was padded; valid
        // visible keys give m_i ~ N(0,1)).  Uniform branch for whole block.
        if (causal && kt == qt) {
            int lack = 0;
            #pragma unroll
            for (int i = 0; i < 4; ++i)
                if (m_i[i] <= -5000.0f) lack = 1;
            if (__syncthreads_or(lack)) limit = NTILES;
        }
    }

    // epilogue: normalize and store [B,H,S,64]
    #pragma unroll
    for (int i = 0; i < 4; ++i) {
        float inv = 1.0f / l_i[i];
        float4 r = make_float4(o[i][0] * inv, o[i][1] * inv, o[i][2] * inv, o[i][3] * inv);
        *reinterpret_cast<float4*>(&g_O[(((size_t)bh) * SEQ + q0 + rr + i) * HD + cc]) = r;
    }
}

// ----------------------------------------------------------------------------
// Stage 3: output projection.  out[m, n] = sum_k O[b, k/64, s, k%64] * Wo[k, n]
// ----------------------------------------------------------------------------
__global__ void __launch_bounds__(256) out_proj_kernel(
    const float* __restrict__ Wo, float* __restrict__ out)
{
    __shared__ float As[64][17];
    __shared__ float Bs[16][64];

    const int n0 = blockIdx.x * 64;
    const int m0 = blockIdx.y * 64;
    const int tid = threadIdx.x;
    const int tx = tid & 15, ty = tid >> 4;

    const int arow = tid >> 2, acol = (tid & 3) * 4;
    const int brow = tid >> 4, bcol = (tid & 15) * 4;

    const int m = m0 + arow;
    const int bb = m >> 11;
    const int ss = m & (SEQ - 1);

    float acc[4][4] = {};

    for (int k0 = 0; k0 < DM; k0 += 16) {
        int kidx = k0 + acol;          // always within one head (16 | 64)
        int h = kidx >> 6, d0 = kidx & 63;
        float4 av = *reinterpret_cast<const float4*>(
            &g_O[(((size_t)(bb * NH + h)) * SEQ + ss) * HD + d0]);
        As[arow][acol + 0] = av.x;
        As[arow][acol + 1] = av.y;
        As[arow][acol + 2] = av.z;
        As[arow][acol + 3] = av.w;
        float4 bv = *reinterpret_cast<const float4*>(&Wo[(size_t)(k0 + brow) * DM + n0 + bcol]);
        *reinterpret_cast<float4*>(&Bs[brow][bcol]) = bv;
        __syncthreads();
        #pragma unroll
        for (int kk = 0; kk < 16; ++kk) {
            float a0 = As[ty * 4 + 0][kk];
            float a1 = As[ty * 4 + 1][kk];
            float a2 = As[ty * 4 + 2][kk];
            float a3 = As[ty * 4 + 3][kk];
            float4 b = *reinterpret_cast<float4*>(&Bs[kk][tx * 4]);
            acc[0][0] += a0 * b.x; acc[0][1] += a0 * b.y; acc[0][2] += a0 * b.z; acc[0][3] += a0 * b.w;
            acc[1][0] += a1 * b.x; acc[1][1] += a1 * b.y; acc[1][2] += a1 * b.z; acc[1][3] += a1 * b.w;
            acc[2][0] += a2 * b.x; acc[2][1] += a2 * b.y; acc[2][2] += a2 * b.z; acc[2][3] += a2 * b.w;
            acc[3][0] += a3 * b.x; acc[3][1] += a3 * b.y; acc[3][2] += a3 * b.z; acc[3][3] += a3 * b.w;
        }
        __syncthreads();
    }

    #pragma unroll
    for (int i = 0; i < 4; ++i) {
        int mm = m0 + ty * 4 + i;
        float4 r = make_float4(acc[i][0], acc[i][1], acc[i][2], acc[i][3]);
        *reinterpret_cast<float4*>(&out[(size_t)mm * DM + n0 + tx * 4]) = r;
    }
}

// ----------------------------------------------------------------------------
extern "C" void kernel_launch(void* const* d_in, const int* in_sizes, int n_in,
                              void* d_out, int out_size)
{
    const float* q    = (const float*)d_in[0];
    const float* k    = (const float*)d_in[1];
    const float* v    = (const float*)d_in[2];
    const int*   mask = (const int*)d_in[3];
    const float* Wq   = (const float*)d_in[4];
    const float* Wk   = (const float*)d_in[5];
    const float* Wv   = (const float*)d_in[6];
    const float* Wo   = (const float*)d_in[7];
    const int*   mfut = (const int*)d_in[8];
    float* out = (float*)d_out;

    const int flash_smem = 3 * 64 * 64 * (int)sizeof(float);  // 48KB, no opt-in needed

    qkv_proj_kernel<<<dim3(DM / 64, MTOT / 64, 3), 256>>>(q, k, v, Wq, Wk, Wv);
    flash_kernel<<<dim3(SEQ / 64, BH), 256, flash_smem>>>(mask, mfut);
    out_proj_kernel<<<dim3(DM / 64, MTOT / 64), 256>>>(Wo, out);
}

// round 5
// speedup vs baseline: 1.0419x; 1.0419x over previous
#include <cuda_runtime.h>

// ----------------------------------------------------------------------------
// MultiHeadAttention, fp32. Stage 1/3: 128x128x16 SGEMM (8x8 micro-tile).
// Stage 2: flash attention Br=Bc=64 with transposed-Q smem fragment reads.
// ----------------------------------------------------------------------------

constexpr int BATCH = 2;
constexpr int SEQ   = 2048;
constexpr int DM    = 768;
constexpr int NH    = 12;
constexpr int HD    = 64;
constexpr int BH    = BATCH * NH;   // 24
constexpr int MTOT  = BATCH * SEQ;  // 4096
constexpr int NTILES = SEQ / 64;    // 32
constexpr float NEGV  = -10000.0f;
constexpr float SCALE = 0.125f;     // 1/sqrt(64)

__device__ float g_Q[BATCH * NH * SEQ * HD];
__device__ float g_K[BATCH * NH * SEQ * HD];
__device__ float g_V[BATCH * NH * SEQ * HD];
__device__ float g_O[BATCH * NH * SEQ * HD];

// ----------------------------------------------------------------------------
// Stage 1: QKV projections. 128x128 tile, BK=16, 256 threads, 8x8 per thread.
// grid = (DM/128, MTOT/128, 3).  Writes head-major [B,H,S,64].
// ----------------------------------------------------------------------------
__global__ void __launch_bounds__(256) qkv_proj_kernel(
    const float* __restrict__ q, const float* __restrict__ k, const float* __restrict__ v,
    const float* __restrict__ Wq, const float* __restrict__ Wk, const float* __restrict__ Wv)
{
    __shared__ float As[16 * 128];   // As[k][m]
    __shared__ float Bs[16 * 128];   // Bs[k][n]

    const int z = blockIdx.z;
    const float* X = (z == 0) ? q : (z == 1) ? k : v;
    const float* W = (z == 0) ? Wq : (z == 1) ? Wk : Wv;
    float* out = (z == 0) ? g_Q : (z == 1) ? g_K : g_V;

    const int n0 = blockIdx.x * 128;
    const int m0 = blockIdx.y * 128;
    const int tid = threadIdx.x;
    const int tx = tid & 15, ty = tid >> 4;

    const int am = tid >> 1;            // A row (0..127)
    const int ak = (tid & 1) * 8;       // A k-offset {0,8}
    const int kb = tid >> 5;            // B row (0..7), +8 second
    const int nb = (tid & 31) * 4;      // B col

    float acc[8][8] = {};

    for (int k0 = 0; k0 < DM; k0 += 16) {
        float4 a0 = *reinterpret_cast<const float4*>(&X[(size_t)(m0 + am) * DM + k0 + ak]);
        float4 a1 = *reinterpret_cast<const float4*>(&X[(size_t)(m0 + am) * DM + k0 + ak + 4]);
        As[(ak + 0) * 128 + am] = a0.x;
        As[(ak + 1) * 128 + am] = a0.y;
        As[(ak + 2) * 128 + am] = a0.z;
        As[(ak + 3) * 128 + am] = a0.w;
        As[(ak + 4) * 128 + am] = a1.x;
        As[(ak + 5) * 128 + am] = a1.y;
        As[(ak + 6) * 128 + am] = a1.z;
        As[(ak + 7) * 128 + am] = a1.w;
        float4 b0 = *reinterpret_cast<const float4*>(&W[(size_t)(k0 + kb) * DM + n0 + nb]);
        float4 b1 = *reinterpret_cast<const float4*>(&W[(size_t)(k0 + kb + 8) * DM + n0 + nb]);
        *reinterpret_cast<float4*>(&Bs[kb * 128 + nb]) = b0;
        *reinterpret_cast<float4*>(&Bs[(kb + 8) * 128 + nb]) = b1;
        __syncthreads();

        #pragma unroll
        for (int kk = 0; kk < 16; ++kk) {
            float4 ra0 = *reinterpret_cast<float4*>(&As[kk * 128 + ty * 8]);
            float4 ra1 = *reinterpret_cast<float4*>(&As[kk * 128 + ty * 8 + 4]);
            float4 rb0 = *reinterpret_cast<float4*>(&Bs[kk * 128 + tx * 8]);
            float4 rb1 = *reinterpret_cast<float4*>(&Bs[kk * 128 + tx * 8 + 4]);
            float ar[8] = {ra0.x, ra0.y, ra0.z, ra0.w, ra1.x, ra1.y, ra1.z, ra1.w};
            float br[8] = {rb0.x, rb0.y, rb0.z, rb0.w, rb1.x, rb1.y, rb1.z, rb1.w};
            #pragma unroll
            for (int i = 0; i < 8; ++i)
                #pragma unroll
                for (int j = 0; j < 8; ++j)
                    acc[i][j] += ar[i] * br[j];
        }
        __syncthreads();
    }

    const int ncol = n0 + tx * 8;
    const int head = ncol >> 6;
    const int d0   = ncol & 63;
    #pragma unroll
    for (int i = 0; i < 8; ++i) {
        int m = m0 + ty * 8 + i;
        int b = m >> 11;
        int s = m & (SEQ - 1);
        float* dst = &out[(((size_t)(b * NH + head)) * SEQ + s) * HD + d0];
        *reinterpret_cast<float4*>(dst)     = make_float4(acc[i][0], acc[i][1], acc[i][2], acc[i][3]);
        *reinterpret_cast<float4*>(dst + 4) = make_float4(acc[i][4], acc[i][5], acc[i][6], acc[i][7]);
    }
}

// ----------------------------------------------------------------------------
// Stage 2: flash attention.  grid = (SEQ/64, B*H), 256 threads, 48KB smem.
// Qt transposed [d][row] for float4 fragment reads. Ps aliases Kt.
// ----------------------------------------------------------------------------
__global__ void __launch_bounds__(256) flash_kernel(
    const int* __restrict__ attn_mask, const int* __restrict__ mask_future)
{
    extern __shared__ float sm[];
    float* Qt = sm;                 // [64 d][64 row]
    float* Kt = sm + 4096;          // [64 d][64 col]; reused as Ps (row-major)
    float* Vs = sm + 8192;          // [64 row][64 d]
    float* Ps = Kt;

    const int tid = threadIdx.x;
    const int tx = tid & 15, ty = tid >> 4;
    const int rr = ty * 4, cc = tx * 4;
    const int qt = blockIdx.x;
    const int bh = blockIdx.y;
    const int b  = bh / NH;
    const int q0 = qt * 64;
    const bool causal = (mask_future[0] != 0);

    // load Q tile transposed: Qt[d][row]
    {
        int j = tid & 63;
        int dq = (tid >> 6) * 16;
        #pragma unroll
        for (int qd = 0; qd < 4; ++qd) {
            int d = dq + qd * 4;
            float4 qv = *reinterpret_cast<const float4*>(
                &g_Q[(((size_t)bh) * SEQ + q0 + j) * HD + d]);
            Qt[(d + 0) * 64 + j] = qv.x;
            Qt[(d + 1) * 64 + j] = qv.y;
            Qt[(d + 2) * 64 + j] = qv.z;
            Qt[(d + 3) * 64 + j] = qv.w;
        }
    }

    float m_i[4], l_i[4], o[4][4];
    #pragma unroll
    for (int i = 0; i < 4; ++i) {
        m_i[i] = -1e30f;
        l_i[i] = 0.0f;
        o[i][0] = o[i][1] = o[i][2] = o[i][3] = 0.0f;
    }

    // Causal: stop after diagonal tile unless some row has no valid visible key
    // (reference softmax spans ALL keys: future = raw*scale-1e4, padded = -1e4).
    int limit = causal ? (qt + 1) : NTILES;

    for (int kt = 0; kt < NTILES; ++kt) {
        if (kt >= limit) break;
        const int k0 = kt * 64;
        __syncthreads();  // prior GEMM2 reads done before overwriting Kt/Vs

        // K tile -> transposed smem
        {
            int j = tid & 63;
            int dq = (tid >> 6) * 16;
            #pragma unroll
            for (int qd = 0; qd < 4; ++qd) {
                int d = dq + qd * 4;
                float4 kv = *reinterpret_cast<const float4*>(
                    &g_K[(((size_t)bh) * SEQ + k0 + j) * HD + d]);
                Kt[(d + 0) * 64 + j] = kv.x;
                Kt[(d + 1) * 64 + j] = kv.y;
                Kt[(d + 2) * 64 + j] = kv.z;
                Kt[(d + 3) * 64 + j] = kv.w;
            }
        }
        // V tile (row-major)
        #pragma unroll
        for (int qd = 0; qd < 4; ++qd) {
            int fi = tid + qd * 256;
            int row = fi >> 4;
            int col = (fi & 15) * 4;
            *reinterpret_cast<float4*>(&Vs[row * 64 + col]) =
                *reinterpret_cast<const float4*>(&g_V[(((size_t)bh) * SEQ + k0 + row) * HD + col]);
        }
        int mk[4];
        #pragma unroll
        for (int j = 0; j < 4; ++j)
            mk[j] = attn_mask[b * SEQ + k0 + cc + j];
        __syncthreads();

        // GEMM1: S = Q K^T  (4x4 per thread, float4 frags both sides)
        float sacc[4][4] = {};
        #pragma unroll 16
        for (int d = 0; d < 64; ++d) {
            float4 qa = *reinterpret_cast<float4*>(&Qt[d * 64 + rr]);
            float4 kb = *reinterpret_cast<float4*>(&Kt[d * 64 + cc]);
            sacc[0][0] += qa.x * kb.x; sacc[0][1] += qa.x * kb.y; sacc[0][2] += qa.x * kb.z; sacc[0][3] += qa.x * kb.w;
            sacc[1][0] += qa.y * kb.x; sacc[1][1] += qa.y * kb.y; sacc[1][2] += qa.y * kb.z; sacc[1][3] += qa.y * kb.w;
            sacc[2][0] += qa.z * kb.x; sacc[2][1] += qa.z * kb.y; sacc[2][2] += qa.z * kb.z; sacc[2][3] += qa.z * kb.w;
            sacc[3][0] += qa.w * kb.x; sacc[3][1] += qa.w * kb.y; sacc[3][2] += qa.w * kb.z; sacc[3][3] += qa.w * kb.w;
        }
        __syncthreads();  // Kt reads done before Ps (=Kt) writes

        // scale + masks (reference order: scale, ADD causal NEG, SET pad NEG)
        #pragma unroll
        for (int i = 0; i < 4; ++i) {
            int ig = q0 + rr + i;
            #pragma unroll
            for (int j = 0; j < 4; ++j) {
                int jg = k0 + cc + j;
                float sv = sacc[i][j] * SCALE;
                if (causal && jg > ig) sv += NEGV;
                if (mk[j] == 0) sv = NEGV;
                sacc[i][j] = sv;
            }
        }

        // online softmax per row
        #pragma unroll
        for (int i = 0; i < 4; ++i) {
            float tm = fmaxf(fmaxf(sacc[i][0], sacc[i][1]), fmaxf(sacc[i][2], sacc[i][3]));
            #pragma unroll
            for (int off = 8; off; off >>= 1)
                tm = fmaxf(tm, __shfl_xor_sync(0xffffffffu, tm, off));
            float mnew = fmaxf(m_i[i], tm);
            float alpha = __expf(m_i[i] - mnew);
            float ps = 0.0f;
            #pragma unroll
            for (int j = 0; j < 4; ++j) {
                float p = __expf(sacc[i][j] - mnew);
                sacc[i][j] = p;
                ps += p;
            }
            #pragma unroll
            for (int off = 8; off; off >>= 1)
                ps += __shfl_xor_sync(0xffffffffu, ps, off);
            l_i[i] = l_i[i] * alpha + ps;
            m_i[i] = mnew;
            o[i][0] *= alpha; o[i][1] *= alpha; o[i][2] *= alpha; o[i][3] *= alpha;
        }

        // write P (row-major, aliased onto Kt)
        #pragma unroll
        for (int i = 0; i < 4; ++i)
            *reinterpret_cast<float4*>(&Ps[(rr + i) * 64 + cc]) =
                make_float4(sacc[i][0], sacc[i][1], sacc[i][2], sacc[i][3]);
        __syncthreads();

        // GEMM2: O += P V  (P rows via broadcast scalar reads)
        #pragma unroll 16
        for (int j = 0; j < 64; ++j) {
            float a0 = Ps[(rr + 0) * 64 + j];
            float a1 = Ps[(rr + 1) * 64 + j];
            float a2 = Ps[(rr + 2) * 64 + j];
            float a3 = Ps[(rr + 3) * 64 + j];
            float4 vv = *reinterpret_cast<float4*>(&Vs[j * 64 + cc]);
            o[0][0] += a0 * vv.x; o[0][1] += a0 * vv.y; o[0][2] += a0 * vv.z; o[0][3] += a0 * vv.w;
            o[1][0] += a1 * vv.x; o[1][1] += a1 * vv.y; o[1][2] += a1 * vv.z; o[1][3] += a1 * vv.w;
            o[2][0] += a2 * vv.x; o[2][1] += a2 * vv.y; o[2][2] += a2 * vv.z; o[2][3] += a2 * vv.w;
            o[3][0] += a3 * vv.x; o[3][1] += a3 * vv.y; o[3][2] += a3 * vv.z; o[3][3] += a3 * vv.w;
        }

        // all-visible-padded rows attend to future keys (reference semantics)
        if (causal && kt == qt) {
            int lack = 0;
            #pragma unroll
            for (int i = 0; i < 4; ++i)
                if (m_i[i] <= -5000.0f) lack = 1;
            if (__syncthreads_or(lack)) limit = NTILES;
        }
    }

    #pragma unroll
    for (int i = 0; i < 4; ++i) {
        float inv = 1.0f / l_i[i];
        float4 r = make_float4(o[i][0] * inv, o[i][1] * inv, o[i][2] * inv, o[i][3] * inv);
        *reinterpret_cast<float4*>(&g_O[(((size_t)bh) * SEQ + q0 + rr + i) * HD + cc]) = r;
    }
}

// ----------------------------------------------------------------------------
// Stage 3: output projection. Same 128x128x16 SGEMM; A gathered head-major.
// grid = (DM/128, MTOT/128).
// ----------------------------------------------------------------------------
__global__ void __launch_bounds__(256) out_proj_kernel(
    const float* __restrict__ Wo, float* __restrict__ out)
{
    __shared__ float As[16 * 128];
    __shared__ float Bs[16 * 128];

    const int n0 = blockIdx.x * 128;
    const int m0 = blockIdx.y * 128;
    const int tid = threadIdx.x;
    const int tx = tid & 15, ty = tid >> 4;

    const int am = tid >> 1;
    const int ak = (tid & 1) * 8;
    const int kb = tid >> 5;
    const int nb = (tid & 31) * 4;

    const int m = m0 + am;
    const int bb = m >> 11;
    const int ss = m & (SEQ - 1);

    float acc[8][8] = {};

    for (int k0 = 0; k0 < DM; k0 += 16) {
        int kidx = k0 + ak;                 // 8 consecutive k within one head
        int h = kidx >> 6, dd = kidx & 63;
        const float* src = &g_O[(((size_t)(bb * NH + h)) * SEQ + ss) * HD + dd];
        float4 a0 = *reinterpret_cast<const float4*>(src);
        float4 a1 = *reinterpret_cast<const float4*>(src + 4);
        As[(ak + 0) * 128 + am] = a0.x;
        As[(ak + 1) * 128 + am] = a0.y;
        As[(ak + 2) * 128 + am] = a0.z;
        As[(ak + 3) * 128 + am] = a0.w;
        As[(ak + 4) * 128 + am] = a1.x;
        As[(ak + 5) * 128 + am] = a1.y;
        As[(ak + 6) * 128 + am] = a1.z;
        As[(ak + 7) * 128 + am] = a1.w;
        float4 b0 = *reinterpret_cast<const float4*>(&Wo[(size_t)(k0 + kb) * DM + n0 + nb]);
        float4 b1 = *reinterpret_cast<const float4*>(&Wo[(size_t)(k0 + kb + 8) * DM + n0 + nb]);
        *reinterpret_cast<float4*>(&Bs[kb * 128 + nb]) = b0;
        *reinterpret_cast<float4*>(&Bs[(kb + 8) * 128 + nb]) = b1;
        __syncthreads();

        #pragma unroll
        for (int kk = 0; kk < 16; ++kk) {
            float4 ra0 = *reinterpret_cast<float4*>(&As[kk * 128 + ty * 8]);
            float4 ra1 = *reinterpret_cast<float4*>(&As[kk * 128 + ty * 8 + 4]);
            float4 rb0 = *reinterpret_cast<float4*>(&Bs[kk * 128 + tx * 8]);
            float4 rb1 = *reinterpret_cast<float4*>(&Bs[kk * 128 + tx * 8 + 4]);
            float ar[8] = {ra0.x, ra0.y, ra0.z, ra0.w, ra1.x, ra1.y, ra1.z, ra1.w};
            float br[8] = {rb0.x, rb0.y, rb0.z, rb0.w, rb1.x, rb1.y, rb1.z, rb1.w};
            #pragma unroll
            for (int i = 0; i < 8; ++i)
                #pragma unroll
                for (int j = 0; j < 8; ++j)
                    acc[i][j] += ar[i] * br[j];
        }
        __syncthreads();
    }

    #pragma unroll
    for (int i = 0; i < 8; ++i) {
        int mm = m0 + ty * 8 + i;
        float* dst = &out[(size_t)mm * DM + n0 + tx * 8];
        *reinterpret_cast<float4*>(dst)     = make_float4(acc[i][0], acc[i][1], acc[i][2], acc[i][3]);
        *reinterpret_cast<float4*>(dst + 4) = make_float4(acc[i][4], acc[i][5], acc[i][6], acc[i][7]);
    }
}

// ----------------------------------------------------------------------------
extern "C" void kernel_launch(void* const* d_in, const int* in_sizes, int n_in,
                              void* d_out, int out_size)
{
    const float* q    = (const float*)d_in[0];
    const float* k    = (const float*)d_in[1];
    const float* v    = (const float*)d_in[2];
    const int*   mask = (const int*)d_in[3];
    const float* Wq   = (const float*)d_in[4];
    const float* Wk   = (const float*)d_in[5];
    const float* Wv   = (const float*)d_in[6];
    const float* Wo   = (const float*)d_in[7];
    const int*   mfut = (const int*)d_in[8];
    float* out = (float*)d_out;

    const int flash_smem = 3 * 64 * 64 * (int)sizeof(float);  // 48KB

    qkv_proj_kernel<<<dim3(DM / 128, MTOT / 128, 3), 256>>>(q, k, v, Wq, Wk, Wv);
    flash_kernel<<<dim3(SEQ / 64, BH), 256, flash_smem>>>(mask, mfut);
    out_proj_kernel<<<dim3(DM / 128, MTOT / 128), 256>>>(Wo, out);
}